// round 5
// baseline (speedup 1.0000x reference)
#include <cuda_runtime.h>
#include <cuda_bf16.h>
#include <math.h>
#include <stdint.h>

// ---------------- problem constants ----------------
constexpr int B = 512, T = 64, S = 128, A = 32, H = 1024, R = 1024;
constexpr int KP = S + A;     // 160
constexpr int N3 = 3 * R;     // 3072
constexpr int NO = 2 * S;     // 256
constexpr int SK = 4;

constexpr size_t OFF_MEAN  = 0;
constexpr size_t OFF_STD   = OFF_MEAN  + (size_t)B * T * S;
constexpr size_t OFF_STATE = OFF_STD   + (size_t)B * T * S;
constexpr size_t OFF_BEL   = OFF_STATE + (size_t)B * T * S;
constexpr size_t OFF_PREV  = OFF_BEL   + (size_t)B * T * R;

// ---------------- device scratch ----------------
__device__ float g_gi[B * N3];
__device__ float g_gh[B * N3];
__device__ float g_belief[B * R];
__device__ float g_state [B * S];
__device__ float g_msp[SK * B * NO];

// bf16 split activations
__device__ __nv_bfloat16 g_x_hi[B * H],   g_x_lo[B * H];
__device__ __nv_bfloat16 g_bel_hi[B * R], g_bel_lo[B * R];
__device__ __nv_bfloat16 g_h_hi[B * H],   g_h_lo[B * H];
// bf16 split transposed weights  [N][K]
__device__ __nv_bfloat16 g_Wpr_hi[H * KP], g_Wpr_lo[H * KP];
__device__ __nv_bfloat16 g_Wih_hi[N3 * H], g_Wih_lo[N3 * H];
__device__ __nv_bfloat16 g_Whh_hi[N3 * R], g_Whh_lo[N3 * R];
__device__ __nv_bfloat16 g_Wh1_hi[H * R],  g_Wh1_lo[H * R];
__device__ __nv_bfloat16 g_Wou_hi[NO * H], g_Wou_lo[NO * H];

// ---------------- portable PTX helpers (sm_80+ features only) ----------------
__device__ __forceinline__ uint32_t smem_to_u32(const void* p) {
    uint32_t a;
    asm("{ .reg .u64 t; cvta.to.shared.u64 t, %1; cvt.u32.u64 %0, t; }" : "=r"(a) : "l"(p));
    return a;
}
__device__ __forceinline__ void cp16(uint32_t saddr, const void* gaddr) {
    asm volatile("cp.async.cg.shared.global [%0], [%1], 16;" :: "r"(saddr), "l"(gaddr) : "memory");
}
__device__ __forceinline__ void cp_commit() { asm volatile("cp.async.commit_group;" ::: "memory"); }
__device__ __forceinline__ void cp_wait0()  { asm volatile("cp.async.wait_group 0;" ::: "memory"); }

__device__ __forceinline__ void ldsm4(uint32_t a, uint32_t& r0, uint32_t& r1,
                                      uint32_t& r2, uint32_t& r3) {
    asm volatile("ldmatrix.sync.aligned.m8n8.x4.shared.b16 {%0,%1,%2,%3}, [%4];"
                 : "=r"(r0), "=r"(r1), "=r"(r2), "=r"(r3) : "r"(a));
}
__device__ __forceinline__ void mma_bf16(float* c, const uint32_t* a, const uint32_t* b) {
    asm volatile("mma.sync.aligned.m16n8k16.row.col.f32.bf16.bf16.f32 "
                 "{%0,%1,%2,%3},{%4,%5,%6,%7},{%8,%9},{%0,%1,%2,%3};"
                 : "+f"(c[0]), "+f"(c[1]), "+f"(c[2]), "+f"(c[3])
                 : "r"(a[0]), "r"(a[1]), "r"(a[2]), "r"(a[3]), "r"(b[0]), "r"(b[1]));
}
__device__ __forceinline__ float elu1(float v) { return (v > 0.f) ? v : expm1f(v); }

// ---------------- init ----------------
__global__ void init_k(const float* __restrict__ prior_state,
                       const float* __restrict__ belief0) {
    int idx = blockIdx.x * blockDim.x + threadIdx.x;
    if (idx < B * R) {
        float v = belief0[idx];
        g_belief[idx] = v;
        __nv_bfloat16 h = __float2bfloat16(v);
        g_bel_hi[idx] = h;
        g_bel_lo[idx] = __float2bfloat16(v - __bfloat162float(h));
    }
    if (idx < B * S) g_state[idx] = prior_state[idx];
}

// ---------------- weight prep: W[K][N] -> hi/lo[N][K] ----------------
__global__ void prep_w(const float* __restrict__ W, __nv_bfloat16* __restrict__ hi,
                       __nv_bfloat16* __restrict__ lo, int K, int N) {
    int idx = blockIdx.x * blockDim.x + threadIdx.x;
    if (idx >= N * K) return;
    int n = idx / K, k = idx % K;
    float v = W[(size_t)k * N + n];
    __nv_bfloat16 h = __float2bfloat16(v);
    hi[idx] = h;
    lo[idx] = __float2bfloat16(v - __bfloat162float(h));
}

// ---------------- bf16-split tensor-core GEMM, 2-stage cp.async pipeline -----
// C[M, N] = A[M, K] @ B[N, K]^T, 3-pass hi/lo split, fp32 accum.
// EPI: 0 = store acc+bias fp32 (DUAL selects set via blockIdx.z)
//      2 = elu(acc+bias) -> bf16 hi/lo split store
//      3 = split-K partial fp32 store (SPLITK slices via blockIdx.z)
// PACKA: A built on the fly from fp32 [state | action_t] with inline hi/lo split.
template<int BM, int BN, int WRM, int WRN, int EPI, int DUAL, int SPLITK, int PACKA, int MINCTA>
__global__ void __launch_bounds__(WRM * WRN * 32, MINCTA)
mma_gemm(const __nv_bfloat16* __restrict__ Ahi0, const __nv_bfloat16* __restrict__ Alo0,
         const __nv_bfloat16* __restrict__ Bhi0, const __nv_bfloat16* __restrict__ Blo0,
         const float* __restrict__ bias0, float* __restrict__ Cf0,
         __nv_bfloat16* __restrict__ Chi, __nv_bfloat16* __restrict__ Clo,
         const __nv_bfloat16* __restrict__ Ahi1, const __nv_bfloat16* __restrict__ Alo1,
         const __nv_bfloat16* __restrict__ Bhi1, const __nv_bfloat16* __restrict__ Blo1,
         const float* __restrict__ bias1, float* __restrict__ Cf1,
         const float* __restrict__ stateSrc, const float* __restrict__ actSrc, int tstep,
         int M, int N, int K) {
    constexpr int THREADS = WRM * WRN * 32;
    constexpr int WTM = BM / WRM, WTN = BN / WRN;
    constexpr int MF = WTM / 16, NF = WTN / 8;
    constexpr int RS = 80;                         // smem row stride (bytes)
    constexpr uint32_t OFS_AH = 0;
    constexpr uint32_t OFS_AL = (uint32_t)BM * RS;
    constexpr uint32_t OFS_BH = 2u * BM * RS;
    constexpr uint32_t OFS_BL = 2u * BM * RS + (uint32_t)BN * RS;
    constexpr uint32_t BUFSZ  = 2u * (BM + BN) * RS;

    extern __shared__ char smem[];
    const uint32_t sb = smem_to_u32(smem);

    const int tid = threadIdx.x;
    const int wid = tid >> 5, lane = tid & 31;
    const int wm = wid / WRN, wn = wid % WRN;
    const int m0 = blockIdx.y * BM, n0 = blockIdx.x * BN;

    const __nv_bfloat16 *Ahi = Ahi0, *Alo = Alo0, *Bhi = Bhi0, *Blo = Blo0;
    const float* bias = bias0;
    float* Cf = Cf0;
    if (DUAL && blockIdx.z == 1) { Ahi = Ahi1; Alo = Alo1; Bhi = Bhi1; Blo = Blo1; bias = bias1; Cf = Cf1; }

    int kz0 = 0, KS = K;
    if (SPLITK > 1) { KS = K / SPLITK; kz0 = blockIdx.z * KS; }
    const int NC = KS / 32;

    const __nv_bfloat16* s0 = Ahi + (size_t)m0 * K + kz0;
    const __nv_bfloat16* s1 = Alo + (size_t)m0 * K + kz0;
    const __nv_bfloat16* s2 = Bhi + (size_t)n0 * K + kz0;
    const __nv_bfloat16* s3 = Blo + (size_t)n0 * K + kz0;

    float acc[MF][NF][4];
    #pragma unroll
    for (int i = 0; i < MF; i++)
        #pragma unroll
        for (int j = 0; j < NF; j++)
            #pragma unroll
            for (int q = 0; q < 4; q++) acc[i][j][q] = 0.f;

    // B (and, when !PACKA, A) tiles via cp.async
    auto load_async = [&](int c, int buf) {
        uint32_t base = sb + (uint32_t)buf * BUFSZ;
        if constexpr (!PACKA) {
            constexpr int PPT = (BM + BN) * 8 / THREADS;
            #pragma unroll
            for (int i = 0; i < PPT; i++) {
                int p = tid + i * THREADS;
                const __nv_bfloat16* s;
                uint32_t ofs;
                int local;
                if (p < BM * 4)                   { s = s0; ofs = OFS_AH; local = p; }
                else if (p < 2 * BM * 4)          { s = s1; ofs = OFS_AL; local = p - BM * 4; }
                else if (p < 2 * BM * 4 + BN * 4) { s = s2; ofs = OFS_BH; local = p - 2 * BM * 4; }
                else                              { s = s3; ofs = OFS_BL; local = p - 2 * BM * 4 - BN * 4; }
                int row = local >> 2, k16 = local & 3;
                cp16(base + ofs + (uint32_t)row * RS + (uint32_t)k16 * 16,
                     s + (size_t)row * K + c * 32 + k16 * 8);
            }
        } else {
            constexpr int BPPT = BN * 8 / THREADS;
            #pragma unroll
            for (int i = 0; i < BPPT; i++) {
                int p = tid + i * THREADS;
                const __nv_bfloat16* s = (p < BN * 4) ? s2 : s3;
                uint32_t ofs = (p < BN * 4) ? OFS_BH : OFS_BL;
                int local = (p < BN * 4) ? p : p - BN * 4;
                int row = local >> 2, k16 = local & 3;
                cp16(base + ofs + (uint32_t)row * RS + (uint32_t)k16 * 16,
                     s + (size_t)row * K + c * 32 + k16 * 8);
            }
        }
    };

    // PACKA: build A tile from fp32 [state | action] with inline hi/lo split (STS)
    auto load_A_pack = [&](int c, int buf) {
        if constexpr (PACKA) {
            char* bm = smem + (uint32_t)buf * BUFSZ;
            constexpr int APPT = BM * 4 / THREADS;
            #pragma unroll
            for (int i = 0; i < APPT; i++) {
                int slot = tid + i * THREADS;
                int row = slot >> 2, g8 = slot & 3;
                int kb = c * 32 + g8 * 8;
                __nv_bfloat16 hv[8], lv[8];
                #pragma unroll
                for (int j = 0; j < 8; j++) {
                    int col = kb + j;
                    float v = (col < S)
                        ? stateSrc[(size_t)(m0 + row) * S + col]
                        : actSrc[(size_t)(m0 + row) * T * A + (size_t)tstep * A + (col - S)];
                    __nv_bfloat16 h = __float2bfloat16(v);
                    hv[j] = h;
                    lv[j] = __float2bfloat16(v - __bfloat162float(h));
                }
                *(uint4*)(bm + OFS_AH + (uint32_t)row * RS + (uint32_t)g8 * 16) = *(uint4*)hv;
                *(uint4*)(bm + OFS_AL + (uint32_t)row * RS + (uint32_t)g8 * 16) = *(uint4*)lv;
            }
        }
    };

    auto mma_chunk = [&](int buf) {
        uint32_t base = sb + (uint32_t)buf * BUFSZ;
        const int grp = lane >> 3, l8 = lane & 7;
        #pragma unroll
        for (int ks = 0; ks < 2; ks++) {
            uint32_t ahi[MF][4], alo[MF][4], bhi[NF][2], blo[NF][2];
            uint32_t arow = (uint32_t)(wm * WTM + (grp & 1) * 8 + l8);
            uint32_t acol = (uint32_t)(ks * 32 + (grp >> 1) * 16);
            #pragma unroll
            for (int mt = 0; mt < MF; mt++) {
                uint32_t r = (arow + mt * 16) * RS + acol;
                ldsm4(base + OFS_AH + r, ahi[mt][0], ahi[mt][1], ahi[mt][2], ahi[mt][3]);
                ldsm4(base + OFS_AL + r, alo[mt][0], alo[mt][1], alo[mt][2], alo[mt][3]);
            }
            uint32_t brow = (uint32_t)(wn * WTN + (grp >> 1) * 8 + l8);
            uint32_t bcol = (uint32_t)(ks * 32 + (grp & 1) * 16);
            #pragma unroll
            for (int np = 0; np < NF / 2; np++) {
                uint32_t r = (brow + np * 16) * RS + bcol;
                ldsm4(base + OFS_BH + r, bhi[2 * np][0], bhi[2 * np][1],
                      bhi[2 * np + 1][0], bhi[2 * np + 1][1]);
                ldsm4(base + OFS_BL + r, blo[2 * np][0], blo[2 * np][1],
                      blo[2 * np + 1][0], blo[2 * np + 1][1]);
            }
            #pragma unroll
            for (int mt = 0; mt < MF; mt++)
                #pragma unroll
                for (int nt = 0; nt < NF; nt++) {
                    mma_bf16(acc[mt][nt], ahi[mt], bhi[nt]);
                    mma_bf16(acc[mt][nt], ahi[mt], blo[nt]);
                    mma_bf16(acc[mt][nt], alo[mt], bhi[nt]);
                }
        }
    };

    // 2-stage pipeline, one sync per chunk:
    //   wait own cp.async; sync (all tiles of chunk c visible, all warps done
    //   with mma(c-1) on the other buffer); issue loads for c+1 into the other
    //   buffer; run mma(c) to hide the load latency.
    load_A_pack(0, 0);
    load_async(0, 0); cp_commit();
    for (int c = 0; c < NC; c++) {
        cp_wait0();
        __syncthreads();
        if (c + 1 < NC) {
            load_A_pack(c + 1, (c + 1) & 1);
            load_async(c + 1, (c + 1) & 1);
            cp_commit();
        }
        mma_chunk(c & 1);
    }

    // ---- epilogue ----
    #pragma unroll
    for (int mt = 0; mt < MF; mt++)
        #pragma unroll
        for (int nt = 0; nt < NF; nt++) {
            int m = m0 + wm * WTM + mt * 16 + (lane >> 2);
            int n = n0 + wn * WTN + nt * 8 + (lane & 3) * 2;
            if constexpr (EPI == 3) {
                float* Cz = Cf + (size_t)blockIdx.z * M * N;
                float2 v0 = make_float2(acc[mt][nt][0], acc[mt][nt][1]);
                float2 v1 = make_float2(acc[mt][nt][2], acc[mt][nt][3]);
                *(float2*)&Cz[(size_t)m * N + n] = v0;
                *(float2*)&Cz[(size_t)(m + 8) * N + n] = v1;
            } else if constexpr (EPI == 2) {
                float b0 = bias[n], b1 = bias[n + 1];
                float v00 = elu1(acc[mt][nt][0] + b0), v01 = elu1(acc[mt][nt][1] + b1);
                float v10 = elu1(acc[mt][nt][2] + b0), v11 = elu1(acc[mt][nt][3] + b1);
                __nv_bfloat16 h00 = __float2bfloat16(v00), h01 = __float2bfloat16(v01);
                __nv_bfloat16 h10 = __float2bfloat16(v10), h11 = __float2bfloat16(v11);
                __nv_bfloat162 hi0; hi0.x = h00; hi0.y = h01;
                __nv_bfloat162 hi1; hi1.x = h10; hi1.y = h11;
                __nv_bfloat162 lo0, lo1;
                lo0.x = __float2bfloat16(v00 - __bfloat162float(h00));
                lo0.y = __float2bfloat16(v01 - __bfloat162float(h01));
                lo1.x = __float2bfloat16(v10 - __bfloat162float(h10));
                lo1.y = __float2bfloat16(v11 - __bfloat162float(h11));
                *(__nv_bfloat162*)&Chi[(size_t)m * N + n] = hi0;
                *(__nv_bfloat162*)&Clo[(size_t)m * N + n] = lo0;
                *(__nv_bfloat162*)&Chi[(size_t)(m + 8) * N + n] = hi1;
                *(__nv_bfloat162*)&Clo[(size_t)(m + 8) * N + n] = lo1;
            } else {
                float b0 = bias[n], b1 = bias[n + 1];
                float2 v0 = make_float2(acc[mt][nt][0] + b0, acc[mt][nt][1] + b1);
                float2 v1 = make_float2(acc[mt][nt][2] + b0, acc[mt][nt][3] + b1);
                *(float2*)&Cf[(size_t)m * N + n] = v0;
                *(float2*)&Cf[(size_t)(m + 8) * N + n] = v1;
            }
        }
}

// ---------------- GRU gate + belief update (+ bf16 split of new belief) -----
__global__ void gate_k(float* __restrict__ out, int t) {
    int idx = blockIdx.x * blockDim.x + threadIdx.x;
    if (idx >= B * R) return;
    int b = idx / R, r = idx % R;
    size_t base = (size_t)b * N3;
    float ir = g_gi[base + r],          hr = g_gh[base + r];
    float iz = g_gi[base + R + r],      hz = g_gh[base + R + r];
    float in_ = g_gi[base + 2 * R + r], hn = g_gh[base + 2 * R + r];
    float rg = 1.f / (1.f + expf(-(ir + hr)));
    float zg = 1.f / (1.f + expf(-(iz + hz)));
    float ng = tanhf(in_ + rg * hn);
    float old = g_belief[idx];
    float nb = (1.f - zg) * ng + zg * old;
    g_belief[idx] = nb;
    __nv_bfloat16 h = __float2bfloat16(nb);
    g_bel_hi[idx] = h;
    g_bel_lo[idx] = __float2bfloat16(nb - __bfloat162float(h));
    size_t o = (size_t)b * T * R + (size_t)t * R + r;
    out[OFF_BEL + o]  = nb;
    out[OFF_PREV + o] = old;
}

// ---------------- epilogue: reduce split-K, softplus, sample ----------------
__global__ void epi_k(const float* __restrict__ noise,
                      const float* __restrict__ b_out,
                      float* __restrict__ out, int t) {
    int idx = blockIdx.x * blockDim.x + threadIdx.x;
    if (idx >= B * S) return;
    int b = idx / S, s = idx % S;
    float mean = b_out[s];
    float raw  = b_out[S + s];
    #pragma unroll
    for (int z = 0; z < SK; z++) {
        mean += g_msp[(size_t)z * B * NO + (size_t)b * NO + s];
        raw  += g_msp[(size_t)z * B * NO + (size_t)b * NO + S + s];
    }
    float sp  = fmaxf(raw, 0.f) + log1pf(expf(-fabsf(raw)));
    float std = sp + 0.1f;
    float eps = noise[(size_t)b * T * S + (size_t)t * S + s];
    float st  = fmaf(std, eps, mean);
    size_t o = (size_t)b * T * S + (size_t)t * S + s;
    out[OFF_MEAN + o]  = mean;
    out[OFF_STD + o]   = std;
    out[OFF_STATE + o] = st;
    g_state[idx] = st;
}

// ---------------- launch ----------------
extern "C" void kernel_launch(void* const* d_in, const int* in_sizes, int n_in,
                              void* d_out, int out_size) {
    const float* prior_state = (const float*)d_in[0];
    const float* belief0     = (const float*)d_in[1];
    const float* actions     = (const float*)d_in[2];
    const float* noise       = (const float*)d_in[3];
    const float* W_proj = (const float*)d_in[4];
    const float* b_proj = (const float*)d_in[5];
    const float* W_ih   = (const float*)d_in[6];
    const float* b_ih   = (const float*)d_in[7];
    const float* W_hh   = (const float*)d_in[8];
    const float* b_hh   = (const float*)d_in[9];
    const float* W_h1   = (const float*)d_in[10];
    const float* b_h1   = (const float*)d_in[11];
    const float* W_out  = (const float*)d_in[12];
    const float* b_out  = (const float*)d_in[13];
    float* out = (float*)d_out;

    float *p_gi, *p_gh, *p_msp, *p_state;
    __nv_bfloat16 *p_xh, *p_xl, *p_bh, *p_bl, *p_hh, *p_hl;
    __nv_bfloat16 *p_Wpr_h, *p_Wpr_l, *p_Wih_h, *p_Wih_l, *p_Whh_h, *p_Whh_l;
    __nv_bfloat16 *p_Wh1_h, *p_Wh1_l, *p_Wou_h, *p_Wou_l;
    cudaGetSymbolAddress((void**)&p_gi,  g_gi);
    cudaGetSymbolAddress((void**)&p_gh,  g_gh);
    cudaGetSymbolAddress((void**)&p_msp, g_msp);
    cudaGetSymbolAddress((void**)&p_state, g_state);
    cudaGetSymbolAddress((void**)&p_xh,  g_x_hi);
    cudaGetSymbolAddress((void**)&p_xl,  g_x_lo);
    cudaGetSymbolAddress((void**)&p_bh,  g_bel_hi);
    cudaGetSymbolAddress((void**)&p_bl,  g_bel_lo);
    cudaGetSymbolAddress((void**)&p_hh,  g_h_hi);
    cudaGetSymbolAddress((void**)&p_hl,  g_h_lo);
    cudaGetSymbolAddress((void**)&p_Wpr_h, g_Wpr_hi);
    cudaGetSymbolAddress((void**)&p_Wpr_l, g_Wpr_lo);
    cudaGetSymbolAddress((void**)&p_Wih_h, g_Wih_hi);
    cudaGetSymbolAddress((void**)&p_Wih_l, g_Wih_lo);
    cudaGetSymbolAddress((void**)&p_Whh_h, g_Whh_hi);
    cudaGetSymbolAddress((void**)&p_Whh_l, g_Whh_lo);
    cudaGetSymbolAddress((void**)&p_Wh1_h, g_Wh1_hi);
    cudaGetSymbolAddress((void**)&p_Wh1_l, g_Wh1_lo);
    cudaGetSymbolAddress((void**)&p_Wou_h, g_Wou_hi);
    cudaGetSymbolAddress((void**)&p_Wou_l, g_Wou_lo);

    // 2-stage smem: 2 * 2*(BM+BN)*80
    constexpr uint32_t SMEM_BIG = 2u * 2u * (128 + 128) * 80;  // 81920 -> 2 CTA/SM
    constexpr uint32_t SMEM_SML = 2u * 2u * (64 + 64) * 80;    // 40960 -> 5 CTA/SM
    cudaFuncSetAttribute((const void*)mma_gemm<128, 128, 2, 4, 0, 1, 1, 0, 2>,
                         cudaFuncAttributeMaxDynamicSharedMemorySize, SMEM_BIG);
    cudaFuncSetAttribute((const void*)mma_gemm<64, 64, 2, 2, 2, 0, 1, 1, 1>,
                         cudaFuncAttributeMaxDynamicSharedMemorySize, SMEM_SML);
    cudaFuncSetAttribute((const void*)mma_gemm<64, 64, 2, 2, 2, 0, 1, 0, 1>,
                         cudaFuncAttributeMaxDynamicSharedMemorySize, SMEM_SML);
    cudaFuncSetAttribute((const void*)mma_gemm<64, 64, 2, 2, 3, 0, SK, 0, 1>,
                         cudaFuncAttributeMaxDynamicSharedMemorySize, SMEM_SML);

    // one-time per replay: init recurrent state + weight transpose/split
    init_k<<<(B * R + 255) / 256, 256>>>(prior_state, belief0);
    prep_w<<<(H * KP + 255) / 256, 256>>>(W_proj, p_Wpr_h, p_Wpr_l, KP, H);
    prep_w<<<(N3 * H + 255) / 256, 256>>>(W_ih, p_Wih_h, p_Wih_l, H, N3);
    prep_w<<<(N3 * R + 255) / 256, 256>>>(W_hh, p_Whh_h, p_Whh_l, R, N3);
    prep_w<<<(H * R + 255) / 256, 256>>>(W_h1, p_Wh1_h, p_Wh1_l, R, H);
    prep_w<<<(NO * H + 255) / 256, 256>>>(W_out, p_Wou_h, p_Wou_l, H, NO);

    for (int t = 0; t < T; t++) {
        // x = elu([state|action_t] @ W_proj + b_proj) -> bf16 hi/lo (fused pack)
        mma_gemm<64, 64, 2, 2, 2, 0, 1, 1, 1>
            <<<dim3(H / 64, B / 64, 1), 128, SMEM_SML>>>(
                nullptr, nullptr, p_Wpr_h, p_Wpr_l, b_proj, nullptr, p_xh, p_xl,
                nullptr, nullptr, nullptr, nullptr, nullptr, nullptr,
                p_state, actions, t, B, H, KP);

        // gi = x @ W_ih + b_ih ; gh = belief @ W_hh + b_hh (dual via z)
        mma_gemm<128, 128, 2, 4, 0, 1, 1, 0, 2>
            <<<dim3(N3 / 128, B / 128, 2), 256, SMEM_BIG>>>(
                p_xh, p_xl, p_Wih_h, p_Wih_l, b_ih, p_gi, nullptr, nullptr,
                p_bh, p_bl, p_Whh_h, p_Whh_l, b_hh, p_gh,
                nullptr, nullptr, 0, B, N3, H);

        // GRU gates -> new belief (+hi/lo), write beliefs + prev_beliefs
        gate_k<<<(B * R + 255) / 256, 256>>>(out, t);

        // h = elu(belief @ W_h1 + b_h1) -> bf16 hi/lo
        mma_gemm<64, 64, 2, 2, 2, 0, 1, 0, 1>
            <<<dim3(H / 64, B / 64, 1), 128, SMEM_SML>>>(
                p_bh, p_bl, p_Wh1_h, p_Wh1_l, b_h1, nullptr, p_hh, p_hl,
                nullptr, nullptr, nullptr, nullptr, nullptr, nullptr,
                nullptr, nullptr, 0, B, H, R);

        // [mean | raw_std] = h @ W_out  (split-K=4 partials)
        mma_gemm<64, 64, 2, 2, 3, 0, SK, 0, 1>
            <<<dim3(NO / 64, B / 64, SK), 128, SMEM_SML>>>(
                p_hh, p_hl, p_Wou_h, p_Wou_l, nullptr, p_msp, nullptr, nullptr,
                nullptr, nullptr, nullptr, nullptr, nullptr, nullptr,
                nullptr, nullptr, 0, B, NO, H);

        // reduce partials + bias, softplus, reparam sample
        epi_k<<<(B * S + 255) / 256, 256>>>(noise, b_out, out, t);
    }
}